// round 11
// baseline (speedup 1.0000x reference)
#include <cuda_runtime.h>

// out[b, j] = prod_{k<=j} cos(x[b,k]) * cos(params[k])
// Closed form of the circuit: product state after RX/RY layers; CNOT chain maps
// Z_j -> Z_0...Z_j (Heisenberg); single-qubit <Z> after RY(p)RX(x)|0> = cos(p)cos(x).
//
// FINAL FORM (best profiled: 4.45us, regs=32). Evidence across R2-R10:
//  - dur x HBM-rate == ~658 KB for every structural variant -> bytes fixed,
//    duration deltas are DVFS clock-state noise (+-4% ncu, +-0.5us wall).
//  - all pipes <5%, occ irrelevant -> launch-ramp + single DRAM round-trip
//    floor (~8k cycles @NAT). No schedulable work remains.
//  - extra graph nodes (prefix pre-kernel / constant staging) cost more in
//    serialized launch overhead than they save in idle-pipe instructions.
// Structure: 2 rows/thread (80 B, 16B-aligned), 128 blocks x 64 threads =
// 8192 threads, single balanced wave, all LDG.128/STG.128, x loads
// front-batched (MLP=5), no bounds check, two ILP=2 prefix chains.

#define N_WIRES 10

__global__ __launch_bounds__(64) void _QuantumGate_65481071395894_kernel(
    const float* __restrict__ x,      // (16384, 10)
    const float* __restrict__ params, // (10,)
    float* __restrict__ out)          // (16384, 10)
{
    int t = blockIdx.x * blockDim.x + threadIdx.x;   // pair index, exact cover

    // Per-thread unique data FIRST: 2 rows = 80 B -> 5x LDG.128 back-to-back.
    const float4* xr = reinterpret_cast<const float4*>(x + (size_t)t * 2 * N_WIRES);
    float4 v0 = __ldg(xr + 0);
    float4 v1 = __ldg(xr + 1);
    float4 v2 = __ldg(xr + 2);
    float4 v3 = __ldg(xr + 3);
    float4 v4 = __ldg(xr + 4);

    // params: 3 broadcast loads (L2-warm across graph replays)
    float4 p0 = __ldg(reinterpret_cast<const float4*>(params));      // p[0..3]
    float4 p1 = __ldg(reinterpret_cast<const float4*>(params) + 1);  // p[4..7]
    float2 p2 = __ldg(reinterpret_cast<const float2*>(params) + 4);  // p[8..9]

    const float pv[N_WIRES] = {p0.x, p0.y, p0.z, p0.w,
                               p1.x, p1.y, p1.z, p1.w, p2.x, p2.y};
    const float xv[2 * N_WIRES] = {v0.x, v0.y, v0.z, v0.w,
                                   v1.x, v1.y, v1.z, v1.w,
                                   v2.x, v2.y, v2.z, v2.w,
                                   v3.x, v3.y, v3.z, v3.w,
                                   v4.x, v4.y, v4.z, v4.w};

    // 30 MUFU cos; two independent prefix chains (ILP=2 through FMA pipe).
    float o[2 * N_WIRES];
    float r0 = 1.0f, r1 = 1.0f;
#pragma unroll
    for (int k = 0; k < N_WIRES; k++) {
        float s = __cosf(pv[k]);
        r0 *= __cosf(xv[k])           * s; o[k]           = r0;
        r1 *= __cosf(xv[N_WIRES + k]) * s; o[N_WIRES + k] = r1;
    }

    float4* orow = reinterpret_cast<float4*>(out + (size_t)t * 2 * N_WIRES);
    orow[0] = make_float4(o[0],  o[1],  o[2],  o[3]);
    orow[1] = make_float4(o[4],  o[5],  o[6],  o[7]);
    orow[2] = make_float4(o[8],  o[9],  o[10], o[11]);
    orow[3] = make_float4(o[12], o[13], o[14], o[15]);
    orow[4] = make_float4(o[16], o[17], o[18], o[19]);
}

extern "C" void kernel_launch(void* const* d_in, const int* in_sizes, int n_in,
                              void* d_out, int out_size) {
    const float* x      = (const float*)d_in[0];   // (16384, 10) float32
    const float* params = (const float*)d_in[1];   // (10,) float32
    float* out          = (float*)d_out;           // (16384, 10) float32

    // B = 16384 rows -> 8192 pair-threads -> 128 blocks x 64 threads, exact.
    _QuantumGate_65481071395894_kernel<<<128, 64>>>(x, params, out);
}

// round 12
// speedup vs baseline: 1.0386x; 1.0386x over previous
#include <cuda_runtime.h>

// out[b, j] = prod_{k<=j} cos(x[b,k]) * cos(params[k])
// Closed form of the circuit: product state after RX/RY layers; CNOT chain maps
// Z_j -> Z_0...Z_j (Heisenberg); single-qubit <Z> after RY(p)RX(x)|0> = cos(p)cos(x).
//
// CONVERGED FINAL FORM (best profiled: 4.45-4.48us, regs=32). R2-R11 evidence:
//  - bit-identical binary re-measured 3x: ncu 4.45/4.64/4.48, wall
//    6.85/6.66/6.88 -> wall-minus-ncu gap is harness replay overhead noise.
//  - dur x HBM-rate == ~658 KB for every structural variant -> bytes fixed;
//    all pipes <5%; launch-ramp + single-DRAM-round-trip floor.
//  - grid shapes flat, coarsening regresses, factoring regresses (regs),
//    extra graph nodes net-negative.
// Structure: 2 rows/thread (80 B, 16B-aligned), 128 blocks x 64 threads =
// 8192 threads, single balanced wave, all LDG.128/STG.128, x loads
// front-batched (MLP=5), no bounds check, two ILP=2 prefix chains.

#define N_WIRES 10

__global__ __launch_bounds__(64) void _QuantumGate_65481071395894_kernel(
    const float* __restrict__ x,      // (16384, 10)
    const float* __restrict__ params, // (10,)
    float* __restrict__ out)          // (16384, 10)
{
    int t = blockIdx.x * blockDim.x + threadIdx.x;   // pair index, exact cover

    // Per-thread unique data FIRST: 2 rows = 80 B -> 5x LDG.128 back-to-back.
    const float4* xr = reinterpret_cast<const float4*>(x + (size_t)t * 2 * N_WIRES);
    float4 v0 = __ldg(xr + 0);
    float4 v1 = __ldg(xr + 1);
    float4 v2 = __ldg(xr + 2);
    float4 v3 = __ldg(xr + 3);
    float4 v4 = __ldg(xr + 4);

    // params: 3 broadcast loads (L2-warm across graph replays)
    float4 p0 = __ldg(reinterpret_cast<const float4*>(params));      // p[0..3]
    float4 p1 = __ldg(reinterpret_cast<const float4*>(params) + 1);  // p[4..7]
    float2 p2 = __ldg(reinterpret_cast<const float2*>(params) + 4);  // p[8..9]

    const float pv[N_WIRES] = {p0.x, p0.y, p0.z, p0.w,
                               p1.x, p1.y, p1.z, p1.w, p2.x, p2.y};
    const float xv[2 * N_WIRES] = {v0.x, v0.y, v0.z, v0.w,
                                   v1.x, v1.y, v1.z, v1.w,
                                   v2.x, v2.y, v2.z, v2.w,
                                   v3.x, v3.y, v3.z, v3.w,
                                   v4.x, v4.y, v4.z, v4.w};

    // 30 MUFU cos; two independent prefix chains (ILP=2 through FMA pipe).
    float o[2 * N_WIRES];
    float r0 = 1.0f, r1 = 1.0f;
#pragma unroll
    for (int k = 0; k < N_WIRES; k++) {
        float s = __cosf(pv[k]);
        r0 *= __cosf(xv[k])           * s; o[k]           = r0;
        r1 *= __cosf(xv[N_WIRES + k]) * s; o[N_WIRES + k] = r1;
    }

    float4* orow = reinterpret_cast<float4*>(out + (size_t)t * 2 * N_WIRES);
    orow[0] = make_float4(o[0],  o[1],  o[2],  o[3]);
    orow[1] = make_float4(o[4],  o[5],  o[6],  o[7]);
    orow[2] = make_float4(o[8],  o[9],  o[10], o[11]);
    orow[3] = make_float4(o[12], o[13], o[14], o[15]);
    orow[4] = make_float4(o[16], o[17], o[18], o[19]);
}

extern "C" void kernel_launch(void* const* d_in, const int* in_sizes, int n_in,
                              void* d_out, int out_size) {
    const float* x      = (const float*)d_in[0];   // (16384, 10) float32
    const float* params = (const float*)d_in[1];   // (10,) float32
    float* out          = (float*)d_out;           // (16384, 10) float32

    // B = 16384 rows -> 8192 pair-threads -> 128 blocks x 64 threads, exact.
    _QuantumGate_65481071395894_kernel<<<128, 64>>>(x, params, out);
}